// round 10
// baseline (speedup 1.0000x reference)
#include <cuda_runtime.h>

#define N_NODES 50000
#define E_EDGES 800000
#define F_INN   512
#define HIDD    128

#define NB  592            // 148 SMs x 4 co-resident (guaranteed: 16..48 regs, no smem)
#define NT  256
#define STRIDE (NB * NT)   // 151552
#define EPT 6              // 151552*6 = 909312 >= E_EDGES

// ---------------- scratch (no allocs allowed) ----------------
// Softmax cancellation: the emb[row].w1 + bias part of the edge score is
// constant within each row's softmax group and cancels. Only
// c[n] = sum_{e:row=n} v_e * (feat[col_e] . (gcn_w @ w2)) matters.
__device__ float    g_u2[F_INN];     // gcn_w @ w2
__device__ float    g_p2[N_NODES];   // feat[n] . u2
__device__ float    g_c[N_NODES];    // segment scatter of v*p2[col]
__device__ float    g_s[N_NODES];    // per-row sum of exp(c[col])
__device__ unsigned g_bar;           // grid barrier counter

// Per-block index-dtype detection (16 leading int64 words, L2-cached).
__device__ __forceinline__ int detect_is64(const void* idx) {
    const long long* p = (const long long*)idx;
    int is64 = 1;
#pragma unroll
    for (int i = 0; i < 16; i++) {
        long long v = p[i];
        if (v < 0 || v >= N_NODES) { is64 = 0; break; }
    }
    return is64;
}

// Software grid barrier (all NB blocks co-resident via launch bounds).
__device__ __forceinline__ void gsync(unsigned target) {
    __syncthreads();
    if (threadIdx.x == 0) {
        __threadfence();
        atomicAdd(&g_bar, 1u);
        while (atomicAdd(&g_bar, 0u) < target) __nanosleep(32);
    }
    __syncthreads();
    __threadfence();
}

__global__ void reset_kernel() { g_bar = 0u; }

// ---------------- K1: setup — u2, zero c/s ----------------
__global__ __launch_bounds__(256) void setup_kernel(const float* __restrict__ gcn_w,
                                                    const float* __restrict__ mlp_w) {
    int b = blockIdx.x;
    if (b < 2) {
        int k = b * 256 + threadIdx.x;           // 0..511
        const float* wrow = gcn_w + (size_t)k * HIDD;
        float s2 = 0.f;
#pragma unroll 8
        for (int j = 0; j < HIDD; j++)
            s2 += wrow[j] * mlp_w[HIDD + j];
        g_u2[k] = s2;
    } else {
        int i = (b - 2) * 256 + threadIdx.x;
        if (i < N_NODES) { g_c[i] = 0.f; g_s[i] = 0.f; }
    }
}

// ---------------- K2: p2[n] = feat[n].u2 — 2 nodes/warp, prefetch + PDL ----------------
__global__ __launch_bounds__(256) void p_kernel(const float* __restrict__ feat) {
    __shared__ float su2[F_INN];
    const int w    = threadIdx.x >> 5;
    const int lane = threadIdx.x & 31;
    const int n0   = blockIdx.x * 16 + w * 2;    // 3125*16 == 50000 exactly
    const float* r0 = feat + (size_t)n0 * F_INN;
    const float* r1 = r0 + F_INN;

    float4 f0[4], f1[4];
#pragma unroll
    for (int ch = 0; ch < 4; ch++) {
        int o = ch * 128 + lane * 4;
        f0[ch] = *(const float4*)(r0 + o);
        f1[ch] = *(const float4*)(r1 + o);
    }

    cudaGridDependencySynchronize();             // wait for setup's u2

    for (int i = threadIdx.x; i < F_INN; i += 256)
        su2[i] = g_u2[i];
    __syncthreads();

    float s0 = 0.f, s1 = 0.f;
#pragma unroll
    for (int ch = 0; ch < 4; ch++) {
        int o = ch * 128 + lane * 4;
        s0 += f0[ch].x * su2[o] + f0[ch].y * su2[o + 1] + f0[ch].z * su2[o + 2] + f0[ch].w * su2[o + 3];
        s1 += f1[ch].x * su2[o] + f1[ch].y * su2[o + 1] + f1[ch].z * su2[o + 2] + f1[ch].w * su2[o + 3];
    }
#pragma unroll
    for (int o = 16; o > 0; o >>= 1) {
        s0 += __shfl_xor_sync(0xFFFFFFFFu, s0, o);
        s1 += __shfl_xor_sync(0xFFFFFFFFu, s1, o);
    }
    if (lane == 0) { g_p2[n0] = s0; g_p2[n0 + 1] = s1; }
}

// ---------------- K3: persistent fused edge kernel (3 phases, 2 barriers) ----------------
__global__ void __launch_bounds__(NT, 4)
edge_kernel(const void*  __restrict__ idx,
            const float* __restrict__ vals,
            float*       __restrict__ out) {
    const int t = blockIdx.x * NT + threadIdx.x;

    // ---- prefetch edge list into registers (independent of p_kernel) ----
    int   er[EPT], ec[EPT];
    float ev[EPT], ex[EPT];
    {
        const int is64 = detect_is64(idx);
#pragma unroll
        for (int i = 0; i < EPT; i++) {
            int e = t + i * STRIDE;
            if (e < E_EDGES) {
                if (is64) {
                    const long long* p = (const long long*)idx;
                    er[i] = (int)p[e];
                    ec[i] = (int)p[E_EDGES + e];
                } else {
                    const int* p = (const int*)idx;
                    er[i] = p[e];
                    ec[i] = p[E_EDGES + e];
                }
                ev[i] = vals[e];
            } else {
                er[i] = -1; ec[i] = 0; ev[i] = 0.f;
            }
        }
    }

    cudaGridDependencySynchronize();             // wait for p2 (and setup's zeros)

    // ---- phase A: c[row] += v * p2[col] ----
#pragma unroll
    for (int i = 0; i < EPT; i++)
        if (er[i] >= 0) atomicAdd(&g_c[er[i]], ev[i] * g_p2[ec[i]]);
    gsync(1u * NB);

    // ---- phase B: ex = exp(c[col]); s[row] += ex ----
#pragma unroll
    for (int i = 0; i < EPT; i++)
        ex[i] = (er[i] >= 0) ? expf(g_c[ec[i]]) : 0.f;
#pragma unroll
    for (int i = 0; i < EPT; i++)
        if (er[i] >= 0) atomicAdd(&g_s[er[i]], ex[i]);
    gsync(2u * NB);

    // ---- phase C: out = v + ex / s[row] ----
#pragma unroll
    for (int i = 0; i < EPT; i++) {
        int e = t + i * STRIDE;
        if (er[i] >= 0) out[e] = ev[i] + __fdividef(ex[i], g_s[er[i]]);
    }
}

// ---------------- launch helpers ----------------
template <typename... Args>
static void launch_pdl(void (*kern)(Args...), int grid, int block, Args... args) {
    cudaLaunchConfig_t cfg = {};
    cfg.gridDim  = dim3(grid);
    cfg.blockDim = dim3(block);
    cudaLaunchAttribute at[1];
    at[0].id = cudaLaunchAttributeProgrammaticStreamSerialization;
    at[0].val.programmaticStreamSerializationAllowed = 1;
    cfg.attrs = at;
    cfg.numAttrs = 1;
    cudaLaunchKernelEx(&cfg, kern, args...);
}

extern "C" void kernel_launch(void* const* d_in, const int* in_sizes, int n_in,
                              void* d_out, int out_size) {
    const float* v_vals = (const float*)d_in[0];
    const float* feat   = (const float*)d_in[1];
    const void*  idx    = d_in[2];
    const float* gcn_w  = (const float*)d_in[n_in - 4];   // 512*128
    const float* mlp_w  = (const float*)d_in[n_in - 2];   // 256
    float*       out    = (float*)d_out;

    reset_kernel<<<1, 1>>>();

    int setup_blocks = 2 + (N_NODES + 255) / 256;
    setup_kernel<<<setup_blocks, 256>>>(gcn_w, mlp_w);

    launch_pdl(p_kernel, N_NODES / 16, 256, feat);

    launch_pdl(edge_kernel, NB, NT, idx, v_vals, out);
}

// round 11
// speedup vs baseline: 1.1026x; 1.1026x over previous
#include <cuda_runtime.h>

#define N_NODES 50000
#define E_EDGES 800000
#define F_INN   512
#define HIDD    128

// ---------------- scratch (no allocs allowed) ----------------
// Softmax cancellation: the emb[row].w1 + bias part of the edge score is
// constant within each row's softmax group and cancels. Only
// c[n] = sum_{e:row=n} v_e * (feat[col_e] . (gcn_w @ w2)) matters.
__device__ float g_u2[F_INN];       // gcn_w @ w2
__device__ float g_p2[N_NODES];     // feat[n] . u2
__device__ float g_c[N_NODES];      // segment scatter of v*p2[col]
__device__ float g_s[N_NODES];      // per-row sum of exp(c[col])
__device__ float g_t[E_EDGES];      // per-edge exp
__device__ int   g_row[E_EDGES];    // decoded rows
__device__ int   g_col[E_EDGES];    // decoded cols

// Per-block index-dtype detection (16 leading int64 words, L2-cached).
__device__ __forceinline__ int detect_is64(const void* idx) {
    const long long* p = (const long long*)idx;
    int is64 = 1;
#pragma unroll
    for (int i = 0; i < 16; i++) {
        long long v = p[i];
        if (v < 0 || v >= N_NODES) { is64 = 0; break; }
    }
    return is64;
}

// ---------------- K1: u2 only (2 blocks) ----------------
__global__ __launch_bounds__(256) void setup_kernel(const float* __restrict__ gcn_w,
                                                    const float* __restrict__ mlp_w) {
    int k = blockIdx.x * 256 + threadIdx.x;      // 0..511
    const float* wrow = gcn_w + (size_t)k * HIDD;
    float s2 = 0.f;
#pragma unroll 8
    for (int j = 0; j < HIDD; j++)
        s2 += wrow[j] * mlp_w[HIDD + j];
    g_u2[k] = s2;
}

// ---------------- K2: p2 = feat . u2 ; also zeroes c/s pre-sync ----------------
__global__ __launch_bounds__(256) void p_kernel(const float* __restrict__ feat) {
    __shared__ float su2[F_INN];
    const int w    = threadIdx.x >> 5;
    const int lane = threadIdx.x & 31;
    const int gtid = blockIdx.x * 256 + threadIdx.x;   // 0..799999
    const int n0   = blockIdx.x * 16 + w * 2;          // 3125*16 == 50000 exactly
    const float* r0 = feat + (size_t)n0 * F_INN;
    const float* r1 = r0 + F_INN;

    // Pre-sync: prefetch feat rows + zero c/s (independent of setup's u2;
    // completes before scatter's post-sync atomics because scatter's PDL sync
    // waits for this entire kernel).
    float4 f0[4], f1[4];
#pragma unroll
    for (int ch = 0; ch < 4; ch++) {
        int o = ch * 128 + lane * 4;
        f0[ch] = *(const float4*)(r0 + o);
        f1[ch] = *(const float4*)(r1 + o);
    }
    if (gtid < N_NODES) { g_c[gtid] = 0.f; g_s[gtid] = 0.f; }

    cudaGridDependencySynchronize();             // wait for setup's u2

    for (int i = threadIdx.x; i < F_INN; i += 256)
        su2[i] = g_u2[i];
    __syncthreads();

    float s0 = 0.f, s1 = 0.f;
#pragma unroll
    for (int ch = 0; ch < 4; ch++) {
        int o = ch * 128 + lane * 4;
        s0 += f0[ch].x * su2[o] + f0[ch].y * su2[o + 1] + f0[ch].z * su2[o + 2] + f0[ch].w * su2[o + 3];
        s1 += f1[ch].x * su2[o] + f1[ch].y * su2[o + 1] + f1[ch].z * su2[o + 2] + f1[ch].w * su2[o + 3];
    }
#pragma unroll
    for (int o = 16; o > 0; o >>= 1) {
        s0 += __shfl_xor_sync(0xFFFFFFFFu, s0, o);
        s1 += __shfl_xor_sync(0xFFFFFFFFu, s1, o);
    }
    if (lane == 0) { g_p2[n0] = s0; g_p2[n0 + 1] = s1; }
}

// ---------------- K3: decode idx (pre-sync), scatter c (EPT=2) ----------------
__global__ __launch_bounds__(256) void scatter_kernel(const void* __restrict__ idx,
                                                      const float* __restrict__ vals) {
    int e0 = (blockIdx.x * 256 + threadIdx.x) * 2;
    if (e0 >= E_EDGES) return;
    // Pre-sync: decode indices + load vals (inputs only).
    int r0, r1, c0, c1;
    if (detect_is64(idx)) {
        const longlong2 pr = *(const longlong2*)((const long long*)idx + e0);
        const longlong2 pc = *(const longlong2*)((const long long*)idx + E_EDGES + e0);
        r0 = (int)pr.x; r1 = (int)pr.y;
        c0 = (int)pc.x; c1 = (int)pc.y;
    } else {
        const int2 pr = *(const int2*)((const int*)idx + e0);
        const int2 pc = *(const int2*)((const int*)idx + E_EDGES + e0);
        r0 = pr.x; r1 = pr.y;
        c0 = pc.x; c1 = pc.y;
    }
    float2 v = *(const float2*)(vals + e0);
    *(int2*)(g_row + e0) = make_int2(r0, r1);
    *(int2*)(g_col + e0) = make_int2(c0, c1);

    cudaGridDependencySynchronize();             // wait for p2 + zeros

    float p20 = g_p2[c0];
    float p21 = g_p2[c1];
    atomicAdd(&g_c[r0], v.x * p20);
    atomicAdd(&g_c[r1], v.y * p21);
}

// ---------------- K4: ex = exp(c[col]); t = ex; s[row] += ex (EPT=2) ----------------
__global__ __launch_bounds__(256) void sumexp_kernel() {
    int e0 = (blockIdx.x * 256 + threadIdx.x) * 2;
    cudaGridDependencySynchronize();             // wait for scatter (c complete)
    if (e0 >= E_EDGES) return;
    int2 r = *(const int2*)(g_row + e0);
    int2 c = *(const int2*)(g_col + e0);
    float cc0 = g_c[c.x];
    float cc1 = g_c[c.y];
    float ex0 = expf(cc0);
    float ex1 = expf(cc1);
    *(float2*)(g_t + e0) = make_float2(ex0, ex1);
    atomicAdd(&g_s[r.x], ex0);
    atomicAdd(&g_s[r.y], ex1);
}

// ---------------- K5: out = v + t/s[row] (EPT=2) ----------------
__global__ __launch_bounds__(256) void out_kernel(const float* __restrict__ vals,
                                                  float* __restrict__ out) {
    int e0 = (blockIdx.x * 256 + threadIdx.x) * 2;
    float2 v = make_float2(0.f, 0.f);
    if (e0 < E_EDGES) v = *(const float2*)(vals + e0);   // input prefetch
    cudaGridDependencySynchronize();             // wait for sumexp (t + s)
    if (e0 >= E_EDGES) return;
    int2 r = *(const int2*)(g_row + e0);
    float2 t = *(const float2*)(g_t + e0);
    float s0 = g_s[r.x];
    float s1 = g_s[r.y];
    *(float2*)(out + e0) = make_float2(v.x + __fdividef(t.x, s0),
                                       v.y + __fdividef(t.y, s1));
}

// ---------------- launch helpers ----------------
template <typename... Args>
static void launch_pdl(void (*kern)(Args...), int grid, int block, Args... args) {
    cudaLaunchConfig_t cfg = {};
    cfg.gridDim  = dim3(grid);
    cfg.blockDim = dim3(block);
    cudaLaunchAttribute at[1];
    at[0].id = cudaLaunchAttributeProgrammaticStreamSerialization;
    at[0].val.programmaticStreamSerializationAllowed = 1;
    cfg.attrs = at;
    cfg.numAttrs = 1;
    cudaLaunchKernelEx(&cfg, kern, args...);
}

extern "C" void kernel_launch(void* const* d_in, const int* in_sizes, int n_in,
                              void* d_out, int out_size) {
    const float* v_vals = (const float*)d_in[0];
    const float* feat   = (const float*)d_in[1];
    const void*  idx    = d_in[2];
    const float* gcn_w  = (const float*)d_in[n_in - 4];   // 512*128
    const float* mlp_w  = (const float*)d_in[n_in - 2];   // 256
    float*       out    = (float*)d_out;

    setup_kernel<<<2, 256>>>(gcn_w, mlp_w);

    launch_pdl(p_kernel, N_NODES / 16, 256, feat);

    int pair_blocks = (E_EDGES / 2 + 255) / 256;          // 1563
    launch_pdl(scatter_kernel, pair_blocks, 256, idx, v_vals);
    launch_pdl(sumexp_kernel, pair_blocks, 256);
    launch_pdl(out_kernel, pair_blocks, 256, v_vals, out);
}